// round 11
// baseline (speedup 1.0000x reference)
#include <cuda_runtime.h>
#include <cstdint>

#define ZB   16384
#define NIN  127
#define NF   128
#define KOUT 128
#define DTS  2080
#define NNF  (NF * NF)
#define RPAIR 8256
#define RPAD  8320          // 65 * 128
#define NHALF  130          // allocated halves (incl. zero pad)
#define NRUN   129          // halves actually processed

// Scratch (device globals)
__device__ __align__(16) float    g_M[KOUT * NNF];              // 8 MB tf32 W@T
__device__ __align__(16) float    g_B[NHALF * 128 * 64];        // packed sym M, permuted
__device__ __align__(16) uint32_t g_pair[RPAD];                 // i | (j<<16)

__device__ __forceinline__ uint32_t f2tf32(float x) {
    uint32_t r;
    asm("cvt.rna.tf32.f32 %0, %1;" : "=r"(r) : "f"(x));
    return r;
}

__device__ __forceinline__ void mma_tf32(float c[4], const uint32_t a[4], const uint32_t b[2]) {
    asm volatile(
        "mma.sync.aligned.m16n8k8.row.col.f32.tf32.tf32.f32 "
        "{%0,%1,%2,%3}, {%4,%5,%6,%7}, {%8,%9}, {%0,%1,%2,%3};"
        : "+f"(c[0]), "+f"(c[1]), "+f"(c[2]), "+f"(c[3])
        : "r"(a[0]), "r"(a[1]), "r"(a[2]), "r"(a[3]), "r"(b[0]), "r"(b[1]));
}

#define NB_SYNC(id)   asm volatile("bar.sync %0, 512;"   :: "r"(id) : "memory")
#define NB_ARRIVE(id) asm volatile("bar.arrive %0, 512;" :: "r"(id) : "memory")

// ---------------------------------------------------------------------------
// Kernel 1: M = W @ T, cp.async double-buffered k-loop.
// 256 threads / 8 warps, warp tile 32m x 64n over a 128m x 128n block tile.
// ---------------------------------------------------------------------------
#define S1_BUF_WORDS (128 * 36)                        // 4608 words per tile
#define S1_SMEM (4 * S1_BUF_WORDS * 4)                 // 2 W bufs + 2 B bufs = 73728 B

__global__ void __launch_bounds__(256, 1) stage1_kernel(
        const float* __restrict__ W, const float* __restrict__ T) {
    extern __shared__ float s1[];
    float* Wb[2] = { s1,                    s1 + S1_BUF_WORDS };
    float* Bb[2] = { s1 + 2 * S1_BUF_WORDS, s1 + 3 * S1_BUF_WORDS };

    const int tid  = threadIdx.x;
    const int lane = tid & 31;
    const int warp = tid >> 5;
    const int gid  = lane >> 2;
    const int tig  = lane & 3;
    const int wm   = warp >> 1;
    const int wn   = warp & 1;
    const int colbase = blockIdx.x * 128;

    float acc[2][8][4];
#pragma unroll
    for (int mf = 0; mf < 2; mf++)
#pragma unroll
        for (int nf = 0; nf < 8; nf++)
#pragma unroll
            for (int q = 0; q < 4; q++) acc[mf][nf][q] = 0.0f;

    auto prefetch = [&](int c, int p) {
        const int kk = c * 32;
        float* Wp = Wb[p];
        float* Bp = Bb[p];
        // W tile [128 m][32 k], 16B chunks, coalesced
#pragma unroll
        for (int t = 0; t < 4; t++) {
            int e = tid + 256 * t;
            int m = e >> 3, kg = e & 7;
            uint32_t dst = (uint32_t)__cvta_generic_to_shared(Wp + m * 36 + kg * 4);
            asm volatile("cp.async.ca.shared.global [%0], [%1], 16;"
                         :: "r"(dst), "l"(W + (size_t)m * DTS + kk + kg * 4));
        }
        // T tile transposed [128 n][32 t], 4B elements (global side coalesced over n)
#pragma unroll
        for (int t = 0; t < 16; t++) {
            int e = tid + 256 * t;
            int tt = e >> 7, n = e & 127;
            uint32_t dst = (uint32_t)__cvta_generic_to_shared(Bp + n * 36 + tt);
            asm volatile("cp.async.ca.shared.global [%0], [%1], 4;"
                         :: "r"(dst), "l"(T + (size_t)(kk + tt) * NNF + colbase + n));
        }
        asm volatile("cp.async.commit_group;" ::: "memory");
    };

    prefetch(0, 0);

    for (int c = 0; c < 65; ++c) {
        asm volatile("cp.async.wait_group 0;" ::: "memory");
        __syncthreads();
        if (c < 64) prefetch(c + 1, (c + 1) & 1);

        const float* Wsm = Wb[c & 1];
        const float* Bsm = Bb[c & 1];

#pragma unroll
        for (int ks = 0; ks < 4; ks++) {
            uint32_t breg[8][2];
#pragma unroll
            for (int nf = 0; nf < 8; nf++) {
                int n0 = wn * 64 + nf * 8 + gid;
                breg[nf][0] = f2tf32(Bsm[n0 * 36 + ks * 8 + tig]);
                breg[nf][1] = f2tf32(Bsm[n0 * 36 + ks * 8 + tig + 4]);
            }
#pragma unroll
            for (int mf = 0; mf < 2; mf++) {
                int r0 = wm * 32 + mf * 16 + gid;
                uint32_t a[4];
                a[0] = f2tf32(Wsm[r0 * 36 + ks * 8 + tig]);
                a[1] = f2tf32(Wsm[(r0 + 8) * 36 + ks * 8 + tig]);
                a[2] = f2tf32(Wsm[r0 * 36 + ks * 8 + tig + 4]);
                a[3] = f2tf32(Wsm[(r0 + 8) * 36 + ks * 8 + tig + 4]);
#pragma unroll
                for (int nf = 0; nf < 8; nf++)
                    mma_tf32(acc[mf][nf], a, breg[nf]);
            }
        }
        __syncthreads();
    }

#pragma unroll
    for (int mf = 0; mf < 2; mf++) {
        int r0 = wm * 32 + mf * 16 + gid;
#pragma unroll
        for (int nf = 0; nf < 8; nf++) {
            int c0 = colbase + wn * 64 + nf * 8 + 2 * tig;
            g_M[r0 * NNF + c0]           = __uint_as_float(f2tf32(acc[mf][nf][0]));
            g_M[r0 * NNF + c0 + 1]       = __uint_as_float(f2tf32(acc[mf][nf][1]));
            g_M[(r0 + 8) * NNF + c0]     = __uint_as_float(f2tf32(acc[mf][nf][2]));
            g_M[(r0 + 8) * NNF + c0 + 1] = __uint_as_float(f2tf32(acc[mf][nf][3]));
        }
    }
}

// ---------------------------------------------------------------------------
// Pair table: r -> (i, j), i <= j, i-major
// ---------------------------------------------------------------------------
__global__ void build_pairs_kernel() {
    int i = blockIdx.x, j = threadIdx.x;
    if (j >= i) {
        int r = i * NF - (i * (i - 1)) / 2 + (j - i);
        g_pair[r] = (uint32_t)i | ((uint32_t)j << 16);
    }
    if (i == 0 && j < RPAD - RPAIR) g_pair[RPAIR + j] = 0;
}

// ---------------------------------------------------------------------------
// Pack (round-9 version): one block per k; smem tile; permuted write.
// ---------------------------------------------------------------------------
#define PACK_SMEM (128 * 129 * 4)   // 66048 B

__global__ void __launch_bounds__(256, 1) pack_kernel() {
    extern __shared__ float tile[];    // [128][129]
    const int k   = blockIdx.x;
    const int tid = threadIdx.x;
    const float* Mk = g_M + (size_t)k * NNF;

#pragma unroll
    for (int e = tid; e < NNF; e += 256) {
        int i = e >> 7, j = e & 127;
        tile[i * 129 + j] = Mk[e];
    }
    __syncthreads();

    for (int r = tid; r < RPAIR; r += 256) {
        uint32_t p = g_pair[r];
        int i = p & 0xFFFF, j = p >> 16;
        float v = tile[i * 129 + j];
        if (i != j) v += tile[j * 129 + i];
        int h  = r >> 6, rr = r & 63;
        int ks = rr >> 3, pos = rr & 7;
        int tg = pos & 3, b = pos >> 2;
        int w = (ks >> 1) * 16 + tg * 4 + 2 * (ks & 1) + b;
        g_B[(size_t)(h * 128 + k) * 64 + w] = __uint_as_float(f2tf32(v));
    }
}

// ---------------------------------------------------------------------------
// Stage 2: warp-specialized (verbatim round 9), 512 threads / 16 warps.
// ---------------------------------------------------------------------------
#define FSTRF 129
#define BSTR  80
#define FSM_WORDS  (128 * FSTRF)          // 16512
#define AH_WORDS   8192
#define BH_WORDS   (128 * BSTR)           // 10240
#define S2_SMEM ((FSM_WORDS + 2 * AH_WORDS + 2 * BH_WORDS) * 4)  // 213504 B

__global__ void __launch_bounds__(512, 1) stage2_kernel(
        const float* __restrict__ feat, float* __restrict__ out) {
    extern __shared__ float sm[];
    float* fsm = sm;
    float* Abuf[2] = { sm + FSM_WORDS, sm + FSM_WORDS + AH_WORDS };
    float* Bbuf[2] = { sm + FSM_WORDS + 2 * AH_WORDS,
                       sm + FSM_WORDS + 2 * AH_WORDS + BH_WORDS };

    const int tid  = threadIdx.x;
    const int lane = tid & 31;
    const int warp = tid >> 5;
    const int gid  = lane >> 2;
    const int tig  = lane & 3;
    const int zbase = blockIdx.x * 128;

    for (int e = tid; e < 128 * 128; e += 512) {
        int z = e >> 7, c = e & 127;
        fsm[z * FSTRF + c] =
            (c == 0) ? 1.0f : feat[(size_t)(zbase + z) * NIN + (c - 1)];
    }
    __syncthreads();

    if (warp >= 8) {
        // ===================== PRODUCER (8 warps) =====================
        const int ptid = tid - 256;
        const int pw   = warp - 8;

        for (int h = 0; h < NRUN; ++h) {
            const int p = h & 1;
            if (h >= 2) NB_SYNC(3 + p);

            {
                float* buf = Bbuf[p];
                const float* src = g_B + (size_t)h * 8192;
#pragma unroll
                for (int t = 0; t < 8; t++) {
                    int cc = ptid + 256 * t;
                    int k = cc >> 4, grp = cc & 15;
                    uint32_t dst = (uint32_t)__cvta_generic_to_shared(buf + k * BSTR + grp * 4);
                    asm volatile("cp.async.cg.shared.global [%0], [%1], 16;"
                                 :: "r"(dst), "l"(src + k * 64 + grp * 4));
                }
                asm volatile("cp.async.commit_group;" ::: "memory");
            }

            {
                float* abuf = Abuf[p];
                const uint32_t* pb = g_pair + h * 64;
#pragma unroll
                for (int step = 0; step < 8; step++) {
                    int g = step * 8 + pw;
                    int mfq = g & 1;
                    int ksq = (g >> 1) & 7;
                    int wmq = g >> 4;
                    uint32_t p0 = __ldg(pb + ksq * 8 + tig);
                    uint32_t p1 = __ldg(pb + ksq * 8 + tig + 4);
                    int i0 = p0 & 0xFFFF, j0 = p0 >> 16;
                    int i1 = p1 & 0xFFFF, j1 = p1 >> 16;
                    const float* fz0 = fsm + (wmq * 32 + mfq * 16 + gid) * FSTRF;
                    const float* fz8 = fz0 + 8 * FSTRF;
                    uint32_t v0 = f2tf32(fz0[i0] * fz0[j0]);
                    uint32_t v1 = f2tf32(fz8[i0] * fz8[j0]);
                    uint32_t v2 = f2tf32(fz0[i1] * fz0[j1]);
                    uint32_t v3 = f2tf32(fz8[i1] * fz8[j1]);
                    uint32_t dst = (uint32_t)__cvta_generic_to_shared(
                        abuf + (size_t)g * 128 + lane * 4);
                    asm volatile("st.shared.v4.b32 [%0], {%1, %2, %3, %4};"
                                 :: "r"(dst), "r"(v0), "r"(v1), "r"(v2), "r"(v3));
                }
            }

            asm volatile("cp.async.wait_group 0;" ::: "memory");
            NB_ARRIVE(1 + p);
        }
    } else {
        // ===================== CONSUMER (8 warps, 32z x 64k) =====================
        const int wm = warp >> 1;
        const int wn = warp & 1;

        float acc[2][8][4];
#pragma unroll
        for (int mf = 0; mf < 2; mf++)
#pragma unroll
            for (int nf = 0; nf < 8; nf++)
#pragma unroll
                for (int q = 0; q < 4; q++) acc[mf][nf][q] = 0.0f;

        for (int h = 0; h < NRUN; ++h) {
            const int p = h & 1;
            NB_SYNC(1 + p);
            const float* abuf = Abuf[p];
            const float* bbuf = Bbuf[p];

#pragma unroll
            for (int klp = 0; klp < 4; klp++) {
                uint32_t a4[4][4];
#pragma unroll
                for (int s = 0; s < 2; s++)
#pragma unroll
                    for (int mf = 0; mf < 2; mf++) {
                        int g = wm * 16 + (2 * klp + s) * 2 + mf;
                        float4 v = *(const float4*)(abuf + (size_t)g * 128 + lane * 4);
                        a4[s * 2 + mf][0] = __float_as_uint(v.x);
                        a4[s * 2 + mf][1] = __float_as_uint(v.y);
                        a4[s * 2 + mf][2] = __float_as_uint(v.z);
                        a4[s * 2 + mf][3] = __float_as_uint(v.w);
                    }
#pragma unroll
                for (int nf = 0; nf < 8; nf++) {
                    int n0 = wn * 64 + nf * 8 + gid;
                    float4 v = *(const float4*)(bbuf + n0 * BSTR + klp * 16 + tig * 4);
                    uint32_t b0[2] = { __float_as_uint(v.x), __float_as_uint(v.y) };
                    uint32_t b1[2] = { __float_as_uint(v.z), __float_as_uint(v.w) };
#pragma unroll
                    for (int mf = 0; mf < 2; mf++) {
                        mma_tf32(acc[mf][nf], a4[0 * 2 + mf], b0);
                        mma_tf32(acc[mf][nf], a4[1 * 2 + mf], b1);
                    }
                }
            }
            NB_ARRIVE(3 + p);
        }

        // Epilogue
#pragma unroll
        for (int mf = 0; mf < 2; mf++) {
            int r0 = wm * 32 + mf * 16 + gid;
#pragma unroll
            for (int nf = 0; nf < 8; nf++) {
                int c0 = wn * 64 + nf * 8 + 2 * tig;
                out[(zbase + r0) * KOUT + c0]         = acc[mf][nf][0];
                out[(zbase + r0) * KOUT + c0 + 1]     = acc[mf][nf][1];
                out[(zbase + r0 + 8) * KOUT + c0]     = acc[mf][nf][2];
                out[(zbase + r0 + 8) * KOUT + c0 + 1] = acc[mf][nf][3];
            }
        }
    }
}

// ---------------------------------------------------------------------------
extern "C" void kernel_launch(void* const* d_in, const int* in_sizes, int n_in,
                              void* d_out, int out_size) {
    const float* feat = nullptr;
    const float* W    = nullptr;
    const float* T    = nullptr;
    for (int i = 0; i < n_in; i++) {
        if      (in_sizes[i] == ZB * NIN)   feat = (const float*)d_in[i];
        else if (in_sizes[i] == KOUT * DTS) W    = (const float*)d_in[i];
        else if (in_sizes[i] == DTS * NNF)  T    = (const float*)d_in[i];
    }
    float* out = (float*)d_out;

    cudaFuncSetAttribute(stage1_kernel,
                         cudaFuncAttributeMaxDynamicSharedMemorySize, S1_SMEM);
    cudaFuncSetAttribute(stage2_kernel,
                         cudaFuncAttributeMaxDynamicSharedMemorySize, S2_SMEM);
    cudaFuncSetAttribute(pack_kernel,
                         cudaFuncAttributeMaxDynamicSharedMemorySize, PACK_SMEM);

    build_pairs_kernel<<<128, 128>>>();
    stage1_kernel<<<128, 256, S1_SMEM>>>(W, T);
    pack_kernel<<<128, 256, PACK_SMEM>>>();
    stage2_kernel<<<128, 512, S2_SMEM>>>(feat, out);
}

// round 12
// speedup vs baseline: 1.1349x; 1.1349x over previous
#include <cuda_runtime.h>
#include <cstdint>

#define ZB   16384
#define NIN  127
#define NF   128
#define KOUT 128
#define DTS  2080
#define NNF  (NF * NF)
#define RPAIR 8256
#define RPAD  8320          // 65 * 128
#define NHALF  130          // allocated halves (incl. zero pad)
#define NRUN   129          // halves actually processed

// Scratch (device globals)
__device__ __align__(16) float    g_M[KOUT * NNF];              // 8 MB tf32 W@T
__device__ __align__(16) float    g_B[NHALF * 128 * 64];        // packed sym M, permuted
__device__ __align__(16) uint32_t g_pair[RPAD];                 // i | (j<<16)

__device__ __forceinline__ uint32_t f2tf32(float x) {
    uint32_t r;
    asm("cvt.rna.tf32.f32 %0, %1;" : "=r"(r) : "f"(x));
    return r;
}

__device__ __forceinline__ void mma_tf32(float c[4], const uint32_t a[4], const uint32_t b[2]) {
    asm volatile(
        "mma.sync.aligned.m16n8k8.row.col.f32.tf32.tf32.f32 "
        "{%0,%1,%2,%3}, {%4,%5,%6,%7}, {%8,%9}, {%0,%1,%2,%3};"
        : "+f"(c[0]), "+f"(c[1]), "+f"(c[2]), "+f"(c[3])
        : "r"(a[0]), "r"(a[1]), "r"(a[2]), "r"(a[3]), "r"(b[0]), "r"(b[1]));
}

#define NB_SYNC(id)   asm volatile("bar.sync %0, 512;"   :: "r"(id) : "memory")
#define NB_ARRIVE(id) asm volatile("bar.arrive %0, 512;" :: "r"(id) : "memory")

// ---------------------------------------------------------------------------
// Kernel 1: M = W @ T, register-pipelined LDG.128 loads (global latency
// hidden behind the previous chunk's MMA work). 256 threads / 8 warps,
// warp tile 32m x 64n over a 128m x 128n block tile. Static smem (36 KB).
// ---------------------------------------------------------------------------
__global__ void __launch_bounds__(256, 1) stage1_kernel(
        const float* __restrict__ W, const float* __restrict__ T) {
    __shared__ float Wsm[128 * 36];
    __shared__ float Bsm[128 * 36];

    const int tid  = threadIdx.x;
    const int lane = tid & 31;
    const int warp = tid >> 5;
    const int gid  = lane >> 2;
    const int tig  = lane & 3;
    const int wm   = warp >> 1;
    const int wn   = warp & 1;
    const int colbase = blockIdx.x * 128;

    float acc[2][8][4];
#pragma unroll
    for (int mf = 0; mf < 2; mf++)
#pragma unroll
        for (int nf = 0; nf < 8; nf++)
#pragma unroll
            for (int q = 0; q < 4; q++) acc[mf][nf][q] = 0.0f;

    // Per-thread tile slices (indices fixed across chunks)
    //   W: t<4: e=tid+256t, m=e>>3, kg=e&7  -> W[m][kk + kg*4 .. +3]
    //   T: t<4: e=tid+256t, tt=e>>5, ng=e&31 -> T[kk+tt][colbase + ng*4 .. +3]
    float4 wreg[4], treg[4];

    auto load_chunk = [&](int c) {
        const int kk = c * 32;
#pragma unroll
        for (int t = 0; t < 4; t++) {
            int e = tid + 256 * t;
            int m = e >> 3, kg = e & 7;
            wreg[t] = *(const float4*)(W + (size_t)m * DTS + kk + kg * 4);
        }
#pragma unroll
        for (int t = 0; t < 4; t++) {
            int e = tid + 256 * t;
            int tt = e >> 5, ng = e & 31;
            treg[t] = *(const float4*)(T + (size_t)(kk + tt) * NNF + colbase + ng * 4);
        }
    };

    load_chunk(0);

    for (int c = 0; c < 65; ++c) {
        __syncthreads();                       // previous compute done with smem
        // store registers -> smem
#pragma unroll
        for (int t = 0; t < 4; t++) {
            int e = tid + 256 * t;
            int m = e >> 3, kg = e & 7;
            *(float4*)(Wsm + m * 36 + kg * 4) = wreg[t];
        }
#pragma unroll
        for (int t = 0; t < 4; t++) {
            int e = tid + 256 * t;
            int tt = e >> 5, ng = e & 31;
            Bsm[(ng * 4 + 0) * 36 + tt] = treg[t].x;
            Bsm[(ng * 4 + 1) * 36 + tt] = treg[t].y;
            Bsm[(ng * 4 + 2) * 36 + tt] = treg[t].z;
            Bsm[(ng * 4 + 3) * 36 + tt] = treg[t].w;
        }
        __syncthreads();                       // tile visible

        if (c < 64) load_chunk(c + 1);         // LDGs in flight during compute

#pragma unroll
        for (int ks = 0; ks < 4; ks++) {
            uint32_t breg[8][2];
#pragma unroll
            for (int nf = 0; nf < 8; nf++) {
                int n0 = wn * 64 + nf * 8 + gid;
                breg[nf][0] = f2tf32(Bsm[n0 * 36 + ks * 8 + tig]);
                breg[nf][1] = f2tf32(Bsm[n0 * 36 + ks * 8 + tig + 4]);
            }
#pragma unroll
            for (int mf = 0; mf < 2; mf++) {
                int r0 = wm * 32 + mf * 16 + gid;
                uint32_t a[4];
                a[0] = f2tf32(Wsm[r0 * 36 + ks * 8 + tig]);
                a[1] = f2tf32(Wsm[(r0 + 8) * 36 + ks * 8 + tig]);
                a[2] = f2tf32(Wsm[r0 * 36 + ks * 8 + tig + 4]);
                a[3] = f2tf32(Wsm[(r0 + 8) * 36 + ks * 8 + tig + 4]);
#pragma unroll
                for (int nf = 0; nf < 8; nf++)
                    mma_tf32(acc[mf][nf], a, breg[nf]);
            }
        }
    }

#pragma unroll
    for (int mf = 0; mf < 2; mf++) {
        int r0 = wm * 32 + mf * 16 + gid;
#pragma unroll
        for (int nf = 0; nf < 8; nf++) {
            int c0 = colbase + wn * 64 + nf * 8 + 2 * tig;
            g_M[r0 * NNF + c0]           = __uint_as_float(f2tf32(acc[mf][nf][0]));
            g_M[r0 * NNF + c0 + 1]       = __uint_as_float(f2tf32(acc[mf][nf][1]));
            g_M[(r0 + 8) * NNF + c0]     = __uint_as_float(f2tf32(acc[mf][nf][2]));
            g_M[(r0 + 8) * NNF + c0 + 1] = __uint_as_float(f2tf32(acc[mf][nf][3]));
        }
    }
}

// ---------------------------------------------------------------------------
// Pair table: r -> (i, j), i <= j, i-major
// ---------------------------------------------------------------------------
__global__ void build_pairs_kernel() {
    int i = blockIdx.x, j = threadIdx.x;
    if (j >= i) {
        int r = i * NF - (i * (i - 1)) / 2 + (j - i);
        g_pair[r] = (uint32_t)i | ((uint32_t)j << 16);
    }
    if (i == 0 && j < RPAD - RPAIR) g_pair[RPAIR + j] = 0;
}

// ---------------------------------------------------------------------------
// Pack (round-9 version): one block per k; smem tile; permuted write.
// ---------------------------------------------------------------------------
#define PACK_SMEM (128 * 129 * 4)   // 66048 B

__global__ void __launch_bounds__(256, 1) pack_kernel() {
    extern __shared__ float tile[];    // [128][129]
    const int k   = blockIdx.x;
    const int tid = threadIdx.x;
    const float* Mk = g_M + (size_t)k * NNF;

#pragma unroll
    for (int e = tid; e < NNF; e += 256) {
        int i = e >> 7, j = e & 127;
        tile[i * 129 + j] = Mk[e];
    }
    __syncthreads();

    for (int r = tid; r < RPAIR; r += 256) {
        uint32_t p = g_pair[r];
        int i = p & 0xFFFF, j = p >> 16;
        float v = tile[i * 129 + j];
        if (i != j) v += tile[j * 129 + i];
        int h  = r >> 6, rr = r & 63;
        int ks = rr >> 3, pos = rr & 7;
        int tg = pos & 3, b = pos >> 2;
        int w = (ks >> 1) * 16 + tg * 4 + 2 * (ks & 1) + b;
        g_B[(size_t)(h * 128 + k) * 64 + w] = __uint_as_float(f2tf32(v));
    }
}

// ---------------------------------------------------------------------------
// Stage 2: warp-specialized (verbatim round 9), 512 threads / 16 warps.
// ---------------------------------------------------------------------------
#define FSTRF 129
#define BSTR  80
#define FSM_WORDS  (128 * FSTRF)          // 16512
#define AH_WORDS   8192
#define BH_WORDS   (128 * BSTR)           // 10240
#define S2_SMEM ((FSM_WORDS + 2 * AH_WORDS + 2 * BH_WORDS) * 4)  // 213504 B

__global__ void __launch_bounds__(512, 1) stage2_kernel(
        const float* __restrict__ feat, float* __restrict__ out) {
    extern __shared__ float sm[];
    float* fsm = sm;
    float* Abuf[2] = { sm + FSM_WORDS, sm + FSM_WORDS + AH_WORDS };
    float* Bbuf[2] = { sm + FSM_WORDS + 2 * AH_WORDS,
                       sm + FSM_WORDS + 2 * AH_WORDS + BH_WORDS };

    const int tid  = threadIdx.x;
    const int lane = tid & 31;
    const int warp = tid >> 5;
    const int gid  = lane >> 2;
    const int tig  = lane & 3;
    const int zbase = blockIdx.x * 128;

    for (int e = tid; e < 128 * 128; e += 512) {
        int z = e >> 7, c = e & 127;
        fsm[z * FSTRF + c] =
            (c == 0) ? 1.0f : feat[(size_t)(zbase + z) * NIN + (c - 1)];
    }
    __syncthreads();

    if (warp >= 8) {
        // ===================== PRODUCER (8 warps) =====================
        const int ptid = tid - 256;
        const int pw   = warp - 8;

        for (int h = 0; h < NRUN; ++h) {
            const int p = h & 1;
            if (h >= 2) NB_SYNC(3 + p);

            {
                float* buf = Bbuf[p];
                const float* src = g_B + (size_t)h * 8192;
#pragma unroll
                for (int t = 0; t < 8; t++) {
                    int cc = ptid + 256 * t;
                    int k = cc >> 4, grp = cc & 15;
                    uint32_t dst = (uint32_t)__cvta_generic_to_shared(buf + k * BSTR + grp * 4);
                    asm volatile("cp.async.cg.shared.global [%0], [%1], 16;"
                                 :: "r"(dst), "l"(src + k * 64 + grp * 4));
                }
                asm volatile("cp.async.commit_group;" ::: "memory");
            }

            {
                float* abuf = Abuf[p];
                const uint32_t* pb = g_pair + h * 64;
#pragma unroll
                for (int step = 0; step < 8; step++) {
                    int g = step * 8 + pw;
                    int mfq = g & 1;
                    int ksq = (g >> 1) & 7;
                    int wmq = g >> 4;
                    uint32_t p0 = __ldg(pb + ksq * 8 + tig);
                    uint32_t p1 = __ldg(pb + ksq * 8 + tig + 4);
                    int i0 = p0 & 0xFFFF, j0 = p0 >> 16;
                    int i1 = p1 & 0xFFFF, j1 = p1 >> 16;
                    const float* fz0 = fsm + (wmq * 32 + mfq * 16 + gid) * FSTRF;
                    const float* fz8 = fz0 + 8 * FSTRF;
                    uint32_t v0 = f2tf32(fz0[i0] * fz0[j0]);
                    uint32_t v1 = f2tf32(fz8[i0] * fz8[j0]);
                    uint32_t v2 = f2tf32(fz0[i1] * fz0[j1]);
                    uint32_t v3 = f2tf32(fz8[i1] * fz8[j1]);
                    uint32_t dst = (uint32_t)__cvta_generic_to_shared(
                        abuf + (size_t)g * 128 + lane * 4);
                    asm volatile("st.shared.v4.b32 [%0], {%1, %2, %3, %4};"
                                 :: "r"(dst), "r"(v0), "r"(v1), "r"(v2), "r"(v3));
                }
            }

            asm volatile("cp.async.wait_group 0;" ::: "memory");
            NB_ARRIVE(1 + p);
        }
    } else {
        // ===================== CONSUMER (8 warps, 32z x 64k) =====================
        const int wm = warp >> 1;
        const int wn = warp & 1;

        float acc[2][8][4];
#pragma unroll
        for (int mf = 0; mf < 2; mf++)
#pragma unroll
            for (int nf = 0; nf < 8; nf++)
#pragma unroll
                for (int q = 0; q < 4; q++) acc[mf][nf][q] = 0.0f;

        for (int h = 0; h < NRUN; ++h) {
            const int p = h & 1;
            NB_SYNC(1 + p);
            const float* abuf = Abuf[p];
            const float* bbuf = Bbuf[p];

#pragma unroll
            for (int klp = 0; klp < 4; klp++) {
                uint32_t a4[4][4];
#pragma unroll
                for (int s = 0; s < 2; s++)
#pragma unroll
                    for (int mf = 0; mf < 2; mf++) {
                        int g = wm * 16 + (2 * klp + s) * 2 + mf;
                        float4 v = *(const float4*)(abuf + (size_t)g * 128 + lane * 4);
                        a4[s * 2 + mf][0] = __float_as_uint(v.x);
                        a4[s * 2 + mf][1] = __float_as_uint(v.y);
                        a4[s * 2 + mf][2] = __float_as_uint(v.z);
                        a4[s * 2 + mf][3] = __float_as_uint(v.w);
                    }
#pragma unroll
                for (int nf = 0; nf < 8; nf++) {
                    int n0 = wn * 64 + nf * 8 + gid;
                    float4 v = *(const float4*)(bbuf + n0 * BSTR + klp * 16 + tig * 4);
                    uint32_t b0[2] = { __float_as_uint(v.x), __float_as_uint(v.y) };
                    uint32_t b1[2] = { __float_as_uint(v.z), __float_as_uint(v.w) };
#pragma unroll
                    for (int mf = 0; mf < 2; mf++) {
                        mma_tf32(acc[mf][nf], a4[0 * 2 + mf], b0);
                        mma_tf32(acc[mf][nf], a4[1 * 2 + mf], b1);
                    }
                }
            }
            NB_ARRIVE(3 + p);
        }

        // Epilogue
#pragma unroll
        for (int mf = 0; mf < 2; mf++) {
            int r0 = wm * 32 + mf * 16 + gid;
#pragma unroll
            for (int nf = 0; nf < 8; nf++) {
                int c0 = wn * 64 + nf * 8 + 2 * tig;
                out[(zbase + r0) * KOUT + c0]         = acc[mf][nf][0];
                out[(zbase + r0) * KOUT + c0 + 1]     = acc[mf][nf][1];
                out[(zbase + r0 + 8) * KOUT + c0]     = acc[mf][nf][2];
                out[(zbase + r0 + 8) * KOUT + c0 + 1] = acc[mf][nf][3];
            }
        }
    }
}

// ---------------------------------------------------------------------------
extern "C" void kernel_launch(void* const* d_in, const int* in_sizes, int n_in,
                              void* d_out, int out_size) {
    const float* feat = nullptr;
    const float* W    = nullptr;
    const float* T    = nullptr;
    for (int i = 0; i < n_in; i++) {
        if      (in_sizes[i] == ZB * NIN)   feat = (const float*)d_in[i];
        else if (in_sizes[i] == KOUT * DTS) W    = (const float*)d_in[i];
        else if (in_sizes[i] == DTS * NNF)  T    = (const float*)d_in[i];
    }
    float* out = (float*)d_out;

    cudaFuncSetAttribute(stage2_kernel,
                         cudaFuncAttributeMaxDynamicSharedMemorySize, S2_SMEM);
    cudaFuncSetAttribute(pack_kernel,
                         cudaFuncAttributeMaxDynamicSharedMemorySize, PACK_SMEM);

    build_pairs_kernel<<<128, 128>>>();
    stage1_kernel<<<128, 256>>>(W, T);
    pack_kernel<<<128, 256, PACK_SMEM>>>();
    stage2_kernel<<<128, 512, S2_SMEM>>>(feat, out);
}

// round 13
// speedup vs baseline: 1.4657x; 1.2915x over previous
#include <cuda_runtime.h>
#include <cstdint>

#define ZB   16384
#define NIN  127
#define NF   128
#define KOUT 128
#define DTS  2080
#define NNF  (NF * NF)
#define RPAIR 8256
#define RPAD  8320          // 65 * 128
#define NHALF  130          // allocated halves (incl. zero pad)
#define NRUN   129          // halves actually processed

// Scratch (device globals)
__device__ __align__(16) float    g_M[KOUT * NNF];              // 8 MB tf32 W@T
__device__ __align__(16) float    g_B[NHALF * 128 * 64];        // packed sym M, permuted
__device__ __align__(16) uint32_t g_pair[RPAD];                 // i | (j<<16)

__device__ __forceinline__ uint32_t f2tf32(float x) {
    uint32_t r;
    asm("cvt.rna.tf32.f32 %0, %1;" : "=r"(r) : "f"(x));
    return r;
}

__device__ __forceinline__ void mma_tf32(float c[4], const uint32_t a[4], const uint32_t b[2]) {
    asm volatile(
        "mma.sync.aligned.m16n8k8.row.col.f32.tf32.tf32.f32 "
        "{%0,%1,%2,%3}, {%4,%5,%6,%7}, {%8,%9}, {%0,%1,%2,%3};"
        : "+f"(c[0]), "+f"(c[1]), "+f"(c[2]), "+f"(c[3])
        : "r"(a[0]), "r"(a[1]), "r"(a[2]), "r"(a[3]), "r"(b[0]), "r"(b[1]));
}

#define NB_SYNC(id)   asm volatile("bar.sync %0, 512;"   :: "r"(id) : "memory")
#define NB_ARRIVE(id) asm volatile("bar.arrive %0, 512;" :: "r"(id) : "memory")

// ---------------------------------------------------------------------------
// Kernel 1: M = W @ T  (original synchronous version — best measured)
// ---------------------------------------------------------------------------
__global__ void __launch_bounds__(256, 1) stage1_kernel(
        const float* __restrict__ W, const float* __restrict__ T) {
    __shared__ float Wsm[128 * 36];
    __shared__ float Bsm[128 * 36];

    const int tid  = threadIdx.x;
    const int lane = tid & 31;
    const int warp = tid >> 5;
    const int gid  = lane >> 2;
    const int tig  = lane & 3;
    const int wm   = warp >> 1;
    const int wn   = warp & 1;
    const int colbase = blockIdx.x * 128;

    float acc[2][8][4];
#pragma unroll
    for (int mf = 0; mf < 2; mf++)
#pragma unroll
        for (int nf = 0; nf < 8; nf++)
#pragma unroll
            for (int q = 0; q < 4; q++) acc[mf][nf][q] = 0.0f;

    for (int kk = 0; kk < DTS; kk += 32) {
        __syncthreads();
#pragma unroll
        for (int e = tid; e < 128 * 32; e += 256) {
            int m = e >> 5, k = e & 31;
            Wsm[m * 36 + k] = W[m * DTS + kk + k];
        }
#pragma unroll
        for (int e = tid; e < 32 * 128; e += 256) {
            int t = e >> 7, n = e & 127;
            Bsm[n * 36 + t] = T[(kk + t) * NNF + colbase + n];
        }
        __syncthreads();

#pragma unroll
        for (int ks = 0; ks < 4; ks++) {
            uint32_t breg[8][2];
#pragma unroll
            for (int nf = 0; nf < 8; nf++) {
                int n0 = wn * 64 + nf * 8 + gid;
                breg[nf][0] = f2tf32(Bsm[n0 * 36 + ks * 8 + tig]);
                breg[nf][1] = f2tf32(Bsm[n0 * 36 + ks * 8 + tig + 4]);
            }
#pragma unroll
            for (int mf = 0; mf < 2; mf++) {
                int r0 = wm * 32 + mf * 16 + gid;
                uint32_t a[4];
                a[0] = f2tf32(Wsm[r0 * 36 + ks * 8 + tig]);
                a[1] = f2tf32(Wsm[(r0 + 8) * 36 + ks * 8 + tig]);
                a[2] = f2tf32(Wsm[r0 * 36 + ks * 8 + tig + 4]);
                a[3] = f2tf32(Wsm[(r0 + 8) * 36 + ks * 8 + tig + 4]);
#pragma unroll
                for (int nf = 0; nf < 8; nf++)
                    mma_tf32(acc[mf][nf], a, breg[nf]);
            }
        }
    }

#pragma unroll
    for (int mf = 0; mf < 2; mf++) {
        int r0 = wm * 32 + mf * 16 + gid;
#pragma unroll
        for (int nf = 0; nf < 8; nf++) {
            int c0 = colbase + wn * 64 + nf * 8 + 2 * tig;
            g_M[r0 * NNF + c0]           = __uint_as_float(f2tf32(acc[mf][nf][0]));
            g_M[r0 * NNF + c0 + 1]       = __uint_as_float(f2tf32(acc[mf][nf][1]));
            g_M[(r0 + 8) * NNF + c0]     = __uint_as_float(f2tf32(acc[mf][nf][2]));
            g_M[(r0 + 8) * NNF + c0 + 1] = __uint_as_float(f2tf32(acc[mf][nf][3]));
        }
    }
}

// ---------------------------------------------------------------------------
// Pair table: r -> (i, j), i <= j, i-major
// ---------------------------------------------------------------------------
__global__ void build_pairs_kernel() {
    int i = blockIdx.x, j = threadIdx.x;
    if (j >= i) {
        int r = i * NF - (i * (i - 1)) / 2 + (j - i);
        g_pair[r] = (uint32_t)i | ((uint32_t)j << 16);
    }
    if (i == 0 && j < RPAD - RPAIR) g_pair[RPAIR + j] = 0;
}

// ---------------------------------------------------------------------------
// Pack (round-9 coalesced version): one block per k; smem tile; permuted write.
// ---------------------------------------------------------------------------
#define PACK_SMEM (128 * 129 * 4)   // 66048 B

__global__ void __launch_bounds__(256, 1) pack_kernel() {
    extern __shared__ float tile[];    // [128][129]
    const int k   = blockIdx.x;
    const int tid = threadIdx.x;
    const float* Mk = g_M + (size_t)k * NNF;

#pragma unroll
    for (int e = tid; e < NNF; e += 256) {
        int i = e >> 7, j = e & 127;
        tile[i * 129 + j] = Mk[e];
    }
    __syncthreads();

    for (int r = tid; r < RPAIR; r += 256) {
        uint32_t p = g_pair[r];
        int i = p & 0xFFFF, j = p >> 16;
        float v = tile[i * 129 + j];
        if (i != j) v += tile[j * 129 + i];
        int h  = r >> 6, rr = r & 63;
        int ks = rr >> 3, pos = rr & 7;
        int tg = pos & 3, b = pos >> 2;
        int w = (ks >> 1) * 16 + tg * 4 + 2 * (ks & 1) + b;
        g_B[(size_t)(h * 128 + k) * 64 + w] = __uint_as_float(f2tf32(v));
    }
}

// ---------------------------------------------------------------------------
// Stage 2: warp-specialized (thrice-confirmed config), 512 threads / 16 warps.
// Warps 0-7: consumers (32z x 64k). Warps 8-15: producers. NRUN=129 halves.
// ---------------------------------------------------------------------------
#define FSTRF 129
#define BSTR  80
#define FSM_WORDS  (128 * FSTRF)          // 16512
#define AH_WORDS   8192
#define BH_WORDS   (128 * BSTR)           // 10240
#define S2_SMEM ((FSM_WORDS + 2 * AH_WORDS + 2 * BH_WORDS) * 4)  // 213504 B

__global__ void __launch_bounds__(512, 1) stage2_kernel(
        const float* __restrict__ feat, float* __restrict__ out) {
    extern __shared__ float sm[];
    float* fsm = sm;
    float* Abuf[2] = { sm + FSM_WORDS, sm + FSM_WORDS + AH_WORDS };
    float* Bbuf[2] = { sm + FSM_WORDS + 2 * AH_WORDS,
                       sm + FSM_WORDS + 2 * AH_WORDS + BH_WORDS };

    const int tid  = threadIdx.x;
    const int lane = tid & 31;
    const int warp = tid >> 5;
    const int gid  = lane >> 2;
    const int tig  = lane & 3;
    const int zbase = blockIdx.x * 128;

    for (int e = tid; e < 128 * 128; e += 512) {
        int z = e >> 7, c = e & 127;
        fsm[z * FSTRF + c] =
            (c == 0) ? 1.0f : feat[(size_t)(zbase + z) * NIN + (c - 1)];
    }
    __syncthreads();

    if (warp >= 8) {
        // ===================== PRODUCER (8 warps) =====================
        const int ptid = tid - 256;
        const int pw   = warp - 8;

        for (int h = 0; h < NRUN; ++h) {
            const int p = h & 1;
            if (h >= 2) NB_SYNC(3 + p);

            {
                float* buf = Bbuf[p];
                const float* src = g_B + (size_t)h * 8192;
#pragma unroll
                for (int t = 0; t < 8; t++) {
                    int cc = ptid + 256 * t;
                    int k = cc >> 4, grp = cc & 15;
                    uint32_t dst = (uint32_t)__cvta_generic_to_shared(buf + k * BSTR + grp * 4);
                    asm volatile("cp.async.cg.shared.global [%0], [%1], 16;"
                                 :: "r"(dst), "l"(src + k * 64 + grp * 4));
                }
                asm volatile("cp.async.commit_group;" ::: "memory");
            }

            {
                float* abuf = Abuf[p];
                const uint32_t* pb = g_pair + h * 64;
#pragma unroll
                for (int step = 0; step < 8; step++) {
                    int g = step * 8 + pw;
                    int mfq = g & 1;
                    int ksq = (g >> 1) & 7;
                    int wmq = g >> 4;
                    uint32_t p0 = __ldg(pb + ksq * 8 + tig);
                    uint32_t p1 = __ldg(pb + ksq * 8 + tig + 4);
                    int i0 = p0 & 0xFFFF, j0 = p0 >> 16;
                    int i1 = p1 & 0xFFFF, j1 = p1 >> 16;
                    const float* fz0 = fsm + (wmq * 32 + mfq * 16 + gid) * FSTRF;
                    const float* fz8 = fz0 + 8 * FSTRF;
                    uint32_t v0 = f2tf32(fz0[i0] * fz0[j0]);
                    uint32_t v1 = f2tf32(fz8[i0] * fz8[j0]);
                    uint32_t v2 = f2tf32(fz0[i1] * fz0[j1]);
                    uint32_t v3 = f2tf32(fz8[i1] * fz8[j1]);
                    uint32_t dst = (uint32_t)__cvta_generic_to_shared(
                        abuf + (size_t)g * 128 + lane * 4);
                    asm volatile("st.shared.v4.b32 [%0], {%1, %2, %3, %4};"
                                 :: "r"(dst), "r"(v0), "r"(v1), "r"(v2), "r"(v3));
                }
            }

            asm volatile("cp.async.wait_group 0;" ::: "memory");
            NB_ARRIVE(1 + p);
        }
    } else {
        // ===================== CONSUMER (8 warps, 32z x 64k) =====================
        const int wm = warp >> 1;
        const int wn = warp & 1;

        float acc[2][8][4];
#pragma unroll
        for (int mf = 0; mf < 2; mf++)
#pragma unroll
            for (int nf = 0; nf < 8; nf++)
#pragma unroll
                for (int q = 0; q < 4; q++) acc[mf][nf][q] = 0.0f;

        for (int h = 0; h < NRUN; ++h) {
            const int p = h & 1;
            NB_SYNC(1 + p);
            const float* abuf = Abuf[p];
            const float* bbuf = Bbuf[p];

#pragma unroll
            for (int klp = 0; klp < 4; klp++) {
                uint32_t a4[4][4];
#pragma unroll
                for (int s = 0; s < 2; s++)
#pragma unroll
                    for (int mf = 0; mf < 2; mf++) {
                        int g = wm * 16 + (2 * klp + s) * 2 + mf;
                        float4 v = *(const float4*)(abuf + (size_t)g * 128 + lane * 4);
                        a4[s * 2 + mf][0] = __float_as_uint(v.x);
                        a4[s * 2 + mf][1] = __float_as_uint(v.y);
                        a4[s * 2 + mf][2] = __float_as_uint(v.z);
                        a4[s * 2 + mf][3] = __float_as_uint(v.w);
                    }
#pragma unroll
                for (int nf = 0; nf < 8; nf++) {
                    int n0 = wn * 64 + nf * 8 + gid;
                    float4 v = *(const float4*)(bbuf + n0 * BSTR + klp * 16 + tig * 4);
                    uint32_t b0[2] = { __float_as_uint(v.x), __float_as_uint(v.y) };
                    uint32_t b1[2] = { __float_as_uint(v.z), __float_as_uint(v.w) };
#pragma unroll
                    for (int mf = 0; mf < 2; mf++) {
                        mma_tf32(acc[mf][nf], a4[0 * 2 + mf], b0);
                        mma_tf32(acc[mf][nf], a4[1 * 2 + mf], b1);
                    }
                }
            }
            NB_ARRIVE(3 + p);
        }

        // Epilogue
#pragma unroll
        for (int mf = 0; mf < 2; mf++) {
            int r0 = wm * 32 + mf * 16 + gid;
#pragma unroll
            for (int nf = 0; nf < 8; nf++) {
                int c0 = wn * 64 + nf * 8 + 2 * tig;
                out[(zbase + r0) * KOUT + c0]         = acc[mf][nf][0];
                out[(zbase + r0) * KOUT + c0 + 1]     = acc[mf][nf][1];
                out[(zbase + r0 + 8) * KOUT + c0]     = acc[mf][nf][2];
                out[(zbase + r0 + 8) * KOUT + c0 + 1] = acc[mf][nf][3];
            }
        }
    }
}

// ---------------------------------------------------------------------------
extern "C" void kernel_launch(void* const* d_in, const int* in_sizes, int n_in,
                              void* d_out, int out_size) {
    const float* feat = nullptr;
    const float* W    = nullptr;
    const float* T    = nullptr;
    for (int i = 0; i < n_in; i++) {
        if      (in_sizes[i] == ZB * NIN)   feat = (const float*)d_in[i];
        else if (in_sizes[i] == KOUT * DTS) W    = (const float*)d_in[i];
        else if (in_sizes[i] == DTS * NNF)  T    = (const float*)d_in[i];
    }
    float* out = (float*)d_out;

    cudaFuncSetAttribute(stage2_kernel,
                         cudaFuncAttributeMaxDynamicSharedMemorySize, S2_SMEM);
    cudaFuncSetAttribute(pack_kernel,
                         cudaFuncAttributeMaxDynamicSharedMemorySize, PACK_SMEM);

    build_pairs_kernel<<<128, 128>>>();
    stage1_kernel<<<128, 256>>>(W, T);
    pack_kernel<<<128, 256, PACK_SMEM>>>();
    stage2_kernel<<<128, 512, S2_SMEM>>>(feat, out);
}

// round 14
// speedup vs baseline: 1.4984x; 1.0224x over previous
#include <cuda_runtime.h>
#include <cstdint>

#define ZB   16384
#define NIN  127
#define NF   128
#define KOUT 128
#define DTS  2080
#define NNF  (NF * NF)
#define RPAIR 8256
#define RPAD  8320          // 65 * 128
#define NHALF  130          // allocated halves (incl. zero pad)
#define NRUN   129          // halves actually processed

// Scratch (device globals)
__device__ __align__(16) float    g_M[KOUT * NNF];              // 8 MB tf32 W@T
__device__ __align__(16) float    g_B[NHALF * 128 * 64];        // packed sym M, permuted
__device__ __align__(16) uint32_t g_pair[RPAD];                 // i | (j<<16)

__device__ __forceinline__ uint32_t f2tf32(float x) {
    uint32_t r;
    asm("cvt.rna.tf32.f32 %0, %1;" : "=r"(r) : "f"(x));
    return r;
}

__device__ __forceinline__ void mma_tf32(float c[4], const uint32_t a[4], const uint32_t b[2]) {
    asm volatile(
        "mma.sync.aligned.m16n8k8.row.col.f32.tf32.tf32.f32 "
        "{%0,%1,%2,%3}, {%4,%5,%6,%7}, {%8,%9}, {%0,%1,%2,%3};"
        : "+f"(c[0]), "+f"(c[1]), "+f"(c[2]), "+f"(c[3])
        : "r"(a[0]), "r"(a[1]), "r"(a[2]), "r"(a[3]), "r"(b[0]), "r"(b[1]));
}

#define NB_SYNC(id)   asm volatile("bar.sync %0, 512;"   :: "r"(id) : "memory")
#define NB_ARRIVE(id) asm volatile("bar.arrive %0, 512;" :: "r"(id) : "memory")

// ---------------------------------------------------------------------------
// Kernel 1: M = W @ T.  512 threads / 16 warps, warp tile 32m x 32n.
// tf32 conversion done ONCE at staging (CVT removed from frag->MMA chain,
// 3x fewer lane-CVTs). Frag loads on stride-36 layout are conflict-free.
// ---------------------------------------------------------------------------
__global__ void __launch_bounds__(512, 1) stage1_kernel(
        const float* __restrict__ W, const float* __restrict__ T) {
    __shared__ float Wsm[128 * 36];
    __shared__ float Bsm[128 * 36];

    const int tid  = threadIdx.x;
    const int lane = tid & 31;
    const int warp = tid >> 5;
    const int gid  = lane >> 2;
    const int tig  = lane & 3;
    const int wm   = warp >> 2;        // 0..3 (m)
    const int wn   = warp & 3;         // 0..3 (n)
    const int colbase = blockIdx.x * 128;

    float acc[2][4][4];
#pragma unroll
    for (int mf = 0; mf < 2; mf++)
#pragma unroll
        for (int nf = 0; nf < 4; nf++)
#pragma unroll
            for (int q = 0; q < 4; q++) acc[mf][nf][q] = 0.0f;

    for (int kk = 0; kk < DTS; kk += 32) {
        __syncthreads();
#pragma unroll
        for (int e = tid; e < 128 * 32; e += 512) {
            int m = e >> 5, k = e & 31;
            Wsm[m * 36 + k] = __uint_as_float(f2tf32(W[(size_t)m * DTS + kk + k]));
        }
#pragma unroll
        for (int e = tid; e < 32 * 128; e += 512) {
            int t = e >> 7, n = e & 127;
            Bsm[n * 36 + t] =
                __uint_as_float(f2tf32(T[(size_t)(kk + t) * NNF + colbase + n]));
        }
        __syncthreads();

#pragma unroll
        for (int ks = 0; ks < 4; ks++) {
            uint32_t breg[4][2];
#pragma unroll
            for (int nf = 0; nf < 4; nf++) {
                int n0 = wn * 32 + nf * 8 + gid;
                breg[nf][0] = __float_as_uint(Bsm[n0 * 36 + ks * 8 + tig]);
                breg[nf][1] = __float_as_uint(Bsm[n0 * 36 + ks * 8 + tig + 4]);
            }
#pragma unroll
            for (int mf = 0; mf < 2; mf++) {
                int r0 = wm * 32 + mf * 16 + gid;
                uint32_t a[4];
                a[0] = __float_as_uint(Wsm[r0 * 36 + ks * 8 + tig]);
                a[1] = __float_as_uint(Wsm[(r0 + 8) * 36 + ks * 8 + tig]);
                a[2] = __float_as_uint(Wsm[r0 * 36 + ks * 8 + tig + 4]);
                a[3] = __float_as_uint(Wsm[(r0 + 8) * 36 + ks * 8 + tig + 4]);
#pragma unroll
                for (int nf = 0; nf < 4; nf++)
                    mma_tf32(acc[mf][nf], a, breg[nf]);
            }
        }
    }

#pragma unroll
    for (int mf = 0; mf < 2; mf++) {
        int r0 = wm * 32 + mf * 16 + gid;
#pragma unroll
        for (int nf = 0; nf < 4; nf++) {
            int c0 = colbase + wn * 32 + nf * 8 + 2 * tig;
            g_M[r0 * NNF + c0]           = __uint_as_float(f2tf32(acc[mf][nf][0]));
            g_M[r0 * NNF + c0 + 1]       = __uint_as_float(f2tf32(acc[mf][nf][1]));
            g_M[(r0 + 8) * NNF + c0]     = __uint_as_float(f2tf32(acc[mf][nf][2]));
            g_M[(r0 + 8) * NNF + c0 + 1] = __uint_as_float(f2tf32(acc[mf][nf][3]));
        }
    }
}

// ---------------------------------------------------------------------------
// Pair table: r -> (i, j), i <= j, i-major
// ---------------------------------------------------------------------------
__global__ void build_pairs_kernel() {
    int i = blockIdx.x, j = threadIdx.x;
    if (j >= i) {
        int r = i * NF - (i * (i - 1)) / 2 + (j - i);
        g_pair[r] = (uint32_t)i | ((uint32_t)j << 16);
    }
    if (i == 0 && j < RPAD - RPAIR) g_pair[RPAIR + j] = 0;
}

// ---------------------------------------------------------------------------
// Pack (round-9 coalesced version): one block per k; smem tile; permuted write.
// ---------------------------------------------------------------------------
#define PACK_SMEM (128 * 129 * 4)   // 66048 B

__global__ void __launch_bounds__(256, 1) pack_kernel() {
    extern __shared__ float tile[];    // [128][129]
    const int k   = blockIdx.x;
    const int tid = threadIdx.x;
    const float* Mk = g_M + (size_t)k * NNF;

#pragma unroll
    for (int e = tid; e < NNF; e += 256) {
        int i = e >> 7, j = e & 127;
        tile[i * 129 + j] = Mk[e];
    }
    __syncthreads();

    for (int r = tid; r < RPAIR; r += 256) {
        uint32_t p = g_pair[r];
        int i = p & 0xFFFF, j = p >> 16;
        float v = tile[i * 129 + j];
        if (i != j) v += tile[j * 129 + i];
        int h  = r >> 6, rr = r & 63;
        int ks = rr >> 3, pos = rr & 7;
        int tg = pos & 3, b = pos >> 2;
        int w = (ks >> 1) * 16 + tg * 4 + 2 * (ks & 1) + b;
        g_B[(size_t)(h * 128 + k) * 64 + w] = __uint_as_float(f2tf32(v));
    }
}

// ---------------------------------------------------------------------------
// Stage 2: warp-specialized (thrice-confirmed config, verbatim), 512 threads.
// Warps 0-7: consumers (32z x 64k). Warps 8-15: producers. NRUN=129 halves.
// ---------------------------------------------------------------------------
#define FSTRF 129
#define BSTR  80
#define FSM_WORDS  (128 * FSTRF)          // 16512
#define AH_WORDS   8192
#define BH_WORDS   (128 * BSTR)           // 10240
#define S2_SMEM ((FSM_WORDS + 2 * AH_WORDS + 2 * BH_WORDS) * 4)  // 213504 B

__global__ void __launch_bounds__(512, 1) stage2_kernel(
        const float* __restrict__ feat, float* __restrict__ out) {
    extern __shared__ float sm[];
    float* fsm = sm;
    float* Abuf[2] = { sm + FSM_WORDS, sm + FSM_WORDS + AH_WORDS };
    float* Bbuf[2] = { sm + FSM_WORDS + 2 * AH_WORDS,
                       sm + FSM_WORDS + 2 * AH_WORDS + BH_WORDS };

    const int tid  = threadIdx.x;
    const int lane = tid & 31;
    const int warp = tid >> 5;
    const int gid  = lane >> 2;
    const int tig  = lane & 3;
    const int zbase = blockIdx.x * 128;

    for (int e = tid; e < 128 * 128; e += 512) {
        int z = e >> 7, c = e & 127;
        fsm[z * FSTRF + c] =
            (c == 0) ? 1.0f : feat[(size_t)(zbase + z) * NIN + (c - 1)];
    }
    __syncthreads();

    if (warp >= 8) {
        // ===================== PRODUCER (8 warps) =====================
        const int ptid = tid - 256;
        const int pw   = warp - 8;

        for (int h = 0; h < NRUN; ++h) {
            const int p = h & 1;
            if (h >= 2) NB_SYNC(3 + p);

            {
                float* buf = Bbuf[p];
                const float* src = g_B + (size_t)h * 8192;
#pragma unroll
                for (int t = 0; t < 8; t++) {
                    int cc = ptid + 256 * t;
                    int k = cc >> 4, grp = cc & 15;
                    uint32_t dst = (uint32_t)__cvta_generic_to_shared(buf + k * BSTR + grp * 4);
                    asm volatile("cp.async.cg.shared.global [%0], [%1], 16;"
                                 :: "r"(dst), "l"(src + k * 64 + grp * 4));
                }
                asm volatile("cp.async.commit_group;" ::: "memory");
            }

            {
                float* abuf = Abuf[p];
                const uint32_t* pb = g_pair + h * 64;
#pragma unroll
                for (int step = 0; step < 8; step++) {
                    int g = step * 8 + pw;
                    int mfq = g & 1;
                    int ksq = (g >> 1) & 7;
                    int wmq = g >> 4;
                    uint32_t p0 = __ldg(pb + ksq * 8 + tig);
                    uint32_t p1 = __ldg(pb + ksq * 8 + tig + 4);
                    int i0 = p0 & 0xFFFF, j0 = p0 >> 16;
                    int i1 = p1 & 0xFFFF, j1 = p1 >> 16;
                    const float* fz0 = fsm + (wmq * 32 + mfq * 16 + gid) * FSTRF;
                    const float* fz8 = fz0 + 8 * FSTRF;
                    uint32_t v0 = f2tf32(fz0[i0] * fz0[j0]);
                    uint32_t v1 = f2tf32(fz8[i0] * fz8[j0]);
                    uint32_t v2 = f2tf32(fz0[i1] * fz0[j1]);
                    uint32_t v3 = f2tf32(fz8[i1] * fz8[j1]);
                    uint32_t dst = (uint32_t)__cvta_generic_to_shared(
                        abuf + (size_t)g * 128 + lane * 4);
                    asm volatile("st.shared.v4.b32 [%0], {%1, %2, %3, %4};"
                                 :: "r"(dst), "r"(v0), "r"(v1), "r"(v2), "r"(v3));
                }
            }

            asm volatile("cp.async.wait_group 0;" ::: "memory");
            NB_ARRIVE(1 + p);
        }
    } else {
        // ===================== CONSUMER (8 warps, 32z x 64k) =====================
        const int wm = warp >> 1;
        const int wn = warp & 1;

        float acc[2][8][4];
#pragma unroll
        for (int mf = 0; mf < 2; mf++)
#pragma unroll
            for (int nf = 0; nf < 8; nf++)
#pragma unroll
                for (int q = 0; q < 4; q++) acc[mf][nf][q] = 0.0f;

        for (int h = 0; h < NRUN; ++h) {
            const int p = h & 1;
            NB_SYNC(1 + p);
            const float* abuf = Abuf[p];
            const float* bbuf = Bbuf[p];

#pragma unroll
            for (int klp = 0; klp < 4; klp++) {
                uint32_t a4[4][4];
#pragma unroll
                for (int s = 0; s < 2; s++)
#pragma unroll
                    for (int mf = 0; mf < 2; mf++) {
                        int g = wm * 16 + (2 * klp + s) * 2 + mf;
                        float4 v = *(const float4*)(abuf + (size_t)g * 128 + lane * 4);
                        a4[s * 2 + mf][0] = __float_as_uint(v.x);
                        a4[s * 2 + mf][1] = __float_as_uint(v.y);
                        a4[s * 2 + mf][2] = __float_as_uint(v.z);
                        a4[s * 2 + mf][3] = __float_as_uint(v.w);
                    }
#pragma unroll
                for (int nf = 0; nf < 8; nf++) {
                    int n0 = wn * 64 + nf * 8 + gid;
                    float4 v = *(const float4*)(bbuf + n0 * BSTR + klp * 16 + tig * 4);
                    uint32_t b0[2] = { __float_as_uint(v.x), __float_as_uint(v.y) };
                    uint32_t b1[2] = { __float_as_uint(v.z), __float_as_uint(v.w) };
#pragma unroll
                    for (int mf = 0; mf < 2; mf++) {
                        mma_tf32(acc[mf][nf], a4[0 * 2 + mf], b0);
                        mma_tf32(acc[mf][nf], a4[1 * 2 + mf], b1);
                    }
                }
            }
            NB_ARRIVE(3 + p);
        }

        // Epilogue
#pragma unroll
        for (int mf = 0; mf < 2; mf++) {
            int r0 = wm * 32 + mf * 16 + gid;
#pragma unroll
            for (int nf = 0; nf < 8; nf++) {
                int c0 = wn * 64 + nf * 8 + 2 * tig;
                out[(zbase + r0) * KOUT + c0]         = acc[mf][nf][0];
                out[(zbase + r0) * KOUT + c0 + 1]     = acc[mf][nf][1];
                out[(zbase + r0 + 8) * KOUT + c0]     = acc[mf][nf][2];
                out[(zbase + r0 + 8) * KOUT + c0 + 1] = acc[mf][nf][3];
            }
        }
    }
}

// ---------------------------------------------------------------------------
extern "C" void kernel_launch(void* const* d_in, const int* in_sizes, int n_in,
                              void* d_out, int out_size) {
    const float* feat = nullptr;
    const float* W    = nullptr;
    const float* T    = nullptr;
    for (int i = 0; i < n_in; i++) {
        if      (in_sizes[i] == ZB * NIN)   feat = (const float*)d_in[i];
        else if (in_sizes[i] == KOUT * DTS) W    = (const float*)d_in[i];
        else if (in_sizes[i] == DTS * NNF)  T    = (const float*)d_in[i];
    }
    float* out = (float*)d_out;

    cudaFuncSetAttribute(stage2_kernel,
                         cudaFuncAttributeMaxDynamicSharedMemorySize, S2_SMEM);
    cudaFuncSetAttribute(pack_kernel,
                         cudaFuncAttributeMaxDynamicSharedMemorySize, PACK_SMEM);

    build_pairs_kernel<<<128, 128>>>();
    stage1_kernel<<<128, 512>>>(W, T);
    pack_kernel<<<128, 256, PACK_SMEM>>>();
    stage2_kernel<<<128, 512, S2_SMEM>>>(feat, out);
}